// round 15
// baseline (speedup 1.0000x reference)
#include <cuda_runtime.h>

#define BATCHN 256
#define SEQN   1024
#define HIDN   200
#define VOCABN 33

#define NWRK  400           // 100 colpairs x 4 chunks
#define WEXT  416           // padded worker region (13 full warps)
#define NIW   50            // i per chunk
#define TPB   512

#define WOPW  36            // padded W_o row (33 -> 36)
#define NROWS ((size_t)BATCHN * SEQN)
#define NOB   (HIDN / 8)    // 25 ob-planes

__device__ float d_E2[VOCABN * HIDN];
__device__ float d_wop[HIDN * WOPW];
__device__ int   d_x_is32 = 0;
__device__ float d_H2[(size_t)NOB * NROWS * 8];   // 210MB, ob-plane interleaved

union F2U { unsigned long long u; float2 f2; };

__device__ __forceinline__ void fma2(unsigned long long& d,
                                     unsigned long long a,
                                     unsigned long long b) {
    asm("fma.rn.f32x2 %0, %1, %2, %0;" : "+l"(d) : "l"(a), "l"(b));
}
__device__ __forceinline__ void add2(unsigned long long& d,
                                     unsigned long long a) {
    asm("add.rn.f32x2 %0, %0, %1;" : "+l"(d) : "l"(a));
}
__device__ __forceinline__ unsigned long long pack2(float x) {
    F2U r; r.f2 = make_float2(x, x); return r.u;
}
__device__ __forceinline__ float fast_tanh(float x) {
    float e = __expf(2.0f * x);
    return 1.0f - __fdividef(2.0f, e + 1.0f);
}

// ---------------------------------------------------------------------------
__global__ void prep_kernel(const float* __restrict__ emb,
                            const float* __restrict__ We,
                            const int* __restrict__ x32) {
    extern __shared__ float psh[];
    float* wsh = psh;
    float* esh = psh + HIDN * HIDN;
    const int v = blockIdx.x, tid = threadIdx.x;

    if (v == 0 && tid < 128) {
        unsigned any = __ballot_sync(0xffffffffu, x32[2 * tid + 1] != 0);
        if ((tid & 31) == 0 && any) atomicOr(&d_x_is32, 1);
    }
    const float4* w4 = reinterpret_cast<const float4*>(We);
    float4* s4 = reinterpret_cast<float4*>(wsh);
    for (int k = tid; k < HIDN * HIDN / 4; k += 256) s4[k] = w4[k];
    for (int k = tid; k < HIDN; k += 256) esh[k] = emb[v * HIDN + k];
    __syncthreads();

    for (int j = tid; j < HIDN; j += 256) {
        float acc = 0.f;
#pragma unroll 8
        for (int e = 0; e < HIDN; e++)
            acc += esh[e] * wsh[e * HIDN + j];
        d_E2[v * HIDN + j] = acc;
    }
}

__global__ void prep2_kernel(const float* __restrict__ Wo) {
    int k = blockIdx.x * blockDim.x + threadIdx.x;
    if (k < HIDN * WOPW) {
        int i = k / WOPW, v = k % WOPW;
        d_wop[k] = (v < VOCABN) ? Wo[i * VOCABN + v] : 0.f;
    }
}

// ---------------------------------------------------------------------------
// Scan v8: single-phase step. 4-lane shfl segment reduces the dot product;
// lane ch==0 finalizes. hdup parity-double-buffered -> ONE barrier per step.
// ---------------------------------------------------------------------------
struct __align__(16) Smem {
    float4 hdup[2][HIDN];            // [parity][col] = {h0,h0,h1,h1}
    float  e2[VOCABN * HIDN];
    float  wop[HIDN * WOPW];
    int    xi[2][SEQN];
};

extern __shared__ unsigned char smem_raw[];

__global__ void __launch_bounds__(TPB, 1)
scan_kernel(const void* __restrict__ xv,
            const float* __restrict__ hidden,
            const float* __restrict__ Wh,
            float* __restrict__ out_logits,
            float* __restrict__ out_hidden,
            int write_h) {
    Smem& s = *reinterpret_cast<Smem*>(smem_raw);
    const int tid = threadIdx.x;
    const int b0  = blockIdx.x * 2;

    // ---- setup ----
    for (int k = tid; k < VOCABN * HIDN; k += TPB) s.e2[k] = d_E2[k];
    for (int k = tid; k < HIDN * WOPW; k += TPB) s.wop[k] = d_wop[k];
    {
        const int is32 = d_x_is32;
        const int* __restrict__ x32 = (const int*)xv;
        const long long* __restrict__ x64 = (const long long*)xv;
        for (int k = tid; k < 2 * SEQN; k += TPB) {
            int r = k >> 10, t = k & (SEQN - 1);
            long long idx = is32 ? (long long)x32[(size_t)(b0 + r) * SEQN + t]
                                 : x64[(size_t)(b0 + r) * SEQN + t];
            s.xi[r][t] = (int)idx;
        }
    }
    for (int j = tid; j < HIDN; j += TPB) {
        float a = hidden[(size_t)b0 * HIDN + j];
        float b = hidden[(size_t)(b0 + 1) * HIDN + j];
        s.hdup[0][j] = make_float4(a, a, b, b);
    }

    // ---- worker geometry: colpair cp (2 cols), chunk ch (50 i) ----
    const int cpr = tid >> 2;                 // raw colpair
    const int cp  = (cpr < 100) ? cpr : 99;   // clamp pad lanes (400..415)
    const int ch  = tid & 3;
    const int i0  = ch * NIW;
    const int col0 = 2 * cp;

    unsigned long long wreg[NIW];
    if (tid < WEXT) {
        const float* wp = Wh + (size_t)i0 * HIDN + col0;
#pragma unroll
        for (int ii = 0; ii < NIW; ii++)
            wreg[ii] = *reinterpret_cast<const unsigned long long*>(wp + (size_t)ii * HIDN);
    }

    const size_t slab = (size_t)b0 << 10;

    __syncthreads();

    // ================= scan loop: ONE barrier per step =================
    for (int t = 0; t < SEQN; t++) {
        const int par = t & 1;
        if (tid < WEXT) {
            F2U a0, a1;
            a0.u = a1.u = 0ull;
            const ulonglong2* hp =
                reinterpret_cast<const ulonglong2*>(&s.hdup[par][i0]);
#pragma unroll
            for (int ii = 0; ii < NIW; ii++) {
                ulonglong2 hd = hp[ii];
                fma2(a0.u, wreg[ii], hd.x);   // row 0, cols {col0,col0+1}
                fma2(a1.u, wreg[ii], hd.y);   // row 1
            }
            // 4-lane segment reduction over chunks (lanes ch=0..3)
            add2(a0.u, __shfl_down_sync(0xffffffffu, a0.u, 2));
            add2(a1.u, __shfl_down_sync(0xffffffffu, a1.u, 2));
            add2(a0.u, __shfl_down_sync(0xffffffffu, a0.u, 1));
            add2(a1.u, __shfl_down_sync(0xffffffffu, a1.u, 1));

            if (ch == 0 && tid < NWRK) {
                const int xi0 = s.xi[0][t];
                const int xi1 = s.xi[1][t];
                F2U xw0, xw1;
                xw0.u = *reinterpret_cast<const unsigned long long*>(&s.e2[xi0 * HIDN + col0]);
                xw1.u = *reinterpret_cast<const unsigned long long*>(&s.e2[xi1 * HIDN + col0]);
                float h00 = fast_tanh(a0.f2.x + xw0.f2.x);   // row0 col0
                float h01 = fast_tanh(a0.f2.y + xw0.f2.y);   // row0 col1
                float h10 = fast_tanh(a1.f2.x + xw1.f2.x);   // row1 col0
                float h11 = fast_tanh(a1.f2.y + xw1.f2.y);   // row1 col1
                s.hdup[par ^ 1][col0]     = make_float4(h00, h00, h10, h10);
                s.hdup[par ^ 1][col0 + 1] = make_float4(h01, h01, h11, h11);
                float* pl = &d_H2[((size_t)(col0 >> 3) * NROWS + slab + t) * 8 + (col0 & 7)];
                *reinterpret_cast<float2*>(pl)                = make_float2(h00, h01);
                *reinterpret_cast<float2*>(pl + (size_t)8192) = make_float2(h10, h11);
                // row1 offset: +1024 rows * 8 = 8192 floats
                if (write_h && t == SEQN - 1) {
                    out_hidden[(size_t)b0 * HIDN + col0]           = h00;
                    out_hidden[(size_t)b0 * HIDN + col0 + 1]       = h01;
                    out_hidden[(size_t)(b0 + 1) * HIDN + col0]     = h10;
                    out_hidden[(size_t)(b0 + 1) * HIDN + col0 + 1] = h11;
                }
            }
        }
        __syncthreads();
    }

    // ================= fused logits tail v7 (unchanged) =================
    float* Obase = out_logits + (size_t)b0 * SEQN * VOCABN;

#pragma unroll 1
    for (int pass = 1; pass >= 0; pass--) {
        const int rA = pass * 1024 + tid;
        const int rB = rA + 512;

        F2U accA[17], accB[17];
#pragma unroll
        for (int p = 0; p < 17; p++) { accA[p].u = 0ull; accB[p].u = 0ull; }

        const float* plane0 = &d_H2[slab * 8];
        float4 nA0 = reinterpret_cast<const float4*>(plane0)[2 * rA];
        float4 nA1 = reinterpret_cast<const float4*>(plane0)[2 * rA + 1];
        float4 nB0 = reinterpret_cast<const float4*>(plane0)[2 * rB];
        float4 nB1 = reinterpret_cast<const float4*>(plane0)[2 * rB + 1];

#pragma unroll 1
        for (int ob = 0; ob < NOB; ob++) {
            float4 a0 = nA0, a1 = nA1, c0 = nB0, c1 = nB1;
            if (ob + 1 < NOB) {
                const float4* pn = reinterpret_cast<const float4*>(
                    &d_H2[((size_t)(ob + 1) * NROWS + slab) * 8]);
                nA0 = pn[2 * rA]; nA1 = pn[2 * rA + 1];
                nB0 = pn[2 * rB]; nB1 = pn[2 * rB + 1];
            }
            const float eA[8] = {a0.x, a0.y, a0.z, a0.w, a1.x, a1.y, a1.z, a1.w};
            const float eB[8] = {c0.x, c0.y, c0.z, c0.w, c1.x, c1.y, c1.z, c1.w};
#pragma unroll
            for (int e = 0; e < 8; e++) {
                const int i = ob * 8 + e;
                const unsigned long long hdA = pack2(eA[e]);
                const unsigned long long hdB = pack2(eB[e]);
                const ulonglong2* wp2 =
                    reinterpret_cast<const ulonglong2*>(&s.wop[i * WOPW]);
#pragma unroll
                for (int q = 0; q < 8; q++) {
                    ulonglong2 w = wp2[q];
                    fma2(accA[2 * q].u,     w.x, hdA);
                    fma2(accA[2 * q + 1].u, w.y, hdA);
                    fma2(accB[2 * q].u,     w.x, hdB);
                    fma2(accB[2 * q + 1].u, w.y, hdB);
                }
                unsigned long long wl =
                    *reinterpret_cast<const unsigned long long*>(&s.wop[i * WOPW + 32]);
                fma2(accA[16].u, wl, hdA);
                fma2(accB[16].u, wl, hdB);
            }
        }

        float* oA = Obase + (size_t)rA * VOCABN;
        float* oB = Obase + (size_t)rB * VOCABN;
#pragma unroll
        for (int p = 0; p < 16; p++) {
            oA[2 * p]     = accA[p].f2.x;
            oA[2 * p + 1] = accA[p].f2.y;
            oB[2 * p]     = accB[p].f2.x;
            oB[2 * p + 1] = accB[p].f2.y;
        }
        oA[32] = accA[16].f2.x;
        oB[32] = accB[16].f2.x;
    }
}

// ---------------------------------------------------------------------------
extern "C" void kernel_launch(void* const* d_in, const int* in_sizes, int n_in,
                              void* d_out, int out_size) {
    const void*  x      = d_in[0];
    const float* hidden = (const float*)d_in[1];
    const float* emb    = (const float*)d_in[2];
    const float* We     = (const float*)d_in[3];
    const float* Wh     = (const float*)d_in[4];
    const float* Wo     = (const float*)d_in[5];

    float* logits = (float*)d_out;
    const long long LOGITS_ELEMS = (long long)BATCHN * SEQN * VOCABN;
    int write_h = (out_size >= (int)(LOGITS_ELEMS + BATCHN * HIDN));
    float* outh = logits + LOGITS_ELEMS;

    const int prep_smem = (HIDN * HIDN + HIDN) * (int)sizeof(float);
    cudaFuncSetAttribute((const void*)prep_kernel,
                         cudaFuncAttributeMaxDynamicSharedMemorySize, prep_smem);
    prep_kernel<<<VOCABN, 256, prep_smem>>>(emb, We, (const int*)x);
    prep2_kernel<<<(HIDN * WOPW + 255) / 256, 256>>>(Wo);

    cudaFuncSetAttribute((const void*)scan_kernel,
                         cudaFuncAttributeMaxDynamicSharedMemorySize,
                         (int)sizeof(Smem));
    scan_kernel<<<BATCHN / 2, TPB, sizeof(Smem)>>>(
        x, hidden, Wh, logits, outh, write_h);
}

// round 16
// speedup vs baseline: 2.1128x; 2.1128x over previous
#include <cuda_runtime.h>

#define BATCHN 256
#define SEQN   1024
#define HIDN   200
#define VOCABN 33

#define NCPG  50            // col groups of 4: 50*4 = 200
#define NCHK  10            // i-chunks of 20
#define NI    20
#define NWRK  500
#define TPB   512

#define WOPW  36            // padded W_o row (33 -> 36)
#define NROWS ((size_t)BATCHN * SEQN)   // 262144 global h-rows
#define NOB   (HIDN / 8)    // 25 ob-planes

__device__ float d_E2[VOCABN * HIDN];
__device__ float d_wop[HIDN * WOPW];
__device__ int   d_x_is32 = 0;
// Block-interleaved H: d_H2[(ob*NROWS + globalrow)*8 + lane], 210MB
__device__ float d_H2[(size_t)NOB * NROWS * 8];

union F2U { unsigned long long u; float2 f2; };

__device__ __forceinline__ void fma2(unsigned long long& d,
                                     unsigned long long a,
                                     unsigned long long b) {
    asm("fma.rn.f32x2 %0, %1, %2, %0;" : "+l"(d) : "l"(a), "l"(b));
}
__device__ __forceinline__ unsigned long long pack2(float x) {
    F2U r; r.f2 = make_float2(x, x); return r.u;
}
__device__ __forceinline__ float fast_tanh(float x) {
    float e = __expf(2.0f * x);
    return 1.0f - __fdividef(2.0f, e + 1.0f);
}

// ---------------------------------------------------------------------------
// prep (merged): blocks 0..32 -> E2 rows (We staged in smem, coalesced);
// block 33 -> wop fill; block 0 also does is32 detection.
// ---------------------------------------------------------------------------
__global__ void prep_kernel(const float* __restrict__ emb,
                            const float* __restrict__ We,
                            const float* __restrict__ Wo,
                            const int* __restrict__ x32) {
    extern __shared__ float psh[];          // [200*200] We + [200] emb row
    const int v = blockIdx.x, tid = threadIdx.x;

    if (v == 33) {
        // wop fill: padded W_o
        for (int k = tid; k < HIDN * WOPW; k += 256) {
            int i = k / WOPW, vv = k % WOPW;
            d_wop[k] = (vv < VOCABN) ? Wo[i * VOCABN + vv] : 0.f;
        }
        return;
    }

    float* wsh = psh;
    float* esh = psh + HIDN * HIDN;

    if (v == 0 && tid < 128) {
        unsigned any = __ballot_sync(0xffffffffu, x32[2 * tid + 1] != 0);
        if ((tid & 31) == 0 && any) atomicOr(&d_x_is32, 1);
    }
    const float4* w4 = reinterpret_cast<const float4*>(We);
    float4* s4 = reinterpret_cast<float4*>(wsh);
    for (int k = tid; k < HIDN * HIDN / 4; k += 256) s4[k] = w4[k];
    for (int k = tid; k < HIDN; k += 256) esh[k] = emb[v * HIDN + k];
    __syncthreads();

    for (int j = tid; j < HIDN; j += 256) {
        float acc = 0.f;
#pragma unroll 8
        for (int e = 0; e < HIDN; e++)
            acc += esh[e] * wsh[e * HIDN + j];
        d_E2[v * HIDN + j] = acc;
    }
}

// ---------------------------------------------------------------------------
// Scan (frozen R7 loop) + fused logits tail v6 (coalesced ob-plane H reads).
// Byte-for-byte the R13 champion.
// ---------------------------------------------------------------------------
struct __align__(16) Smem {
    float4 hdup[HIDN];               // {h0,h0,h1,h1} per column
    float4 part[NCHK][2][NCPG];      // GEMV partials
    float  e2[VOCABN * HIDN];
    float  wop[HIDN * WOPW];         // padded W_o for the tail
    int    xi[2][SEQN];
};

extern __shared__ unsigned char smem_raw[];

__global__ void __launch_bounds__(TPB, 1)
scan_kernel(const void* __restrict__ xv,
            const float* __restrict__ hidden,
            const float* __restrict__ Wh,
            float* __restrict__ out_logits,
            float* __restrict__ out_hidden,
            int write_h) {
    Smem& s = *reinterpret_cast<Smem*>(smem_raw);
    const int tid = threadIdx.x;
    const int b0  = blockIdx.x * 2;

    // ---- setup ----
    for (int k = tid; k < VOCABN * HIDN; k += TPB) s.e2[k] = d_E2[k];
    for (int k = tid; k < HIDN * WOPW; k += TPB) s.wop[k] = d_wop[k];
    {
        const int is32 = d_x_is32;
        const int* __restrict__ x32 = (const int*)xv;
        const long long* __restrict__ x64 = (const long long*)xv;
        for (int k = tid; k < 2 * SEQN; k += TPB) {
            int r = k >> 10, t = k & (SEQN - 1);
            long long idx = is32 ? (long long)x32[(size_t)(b0 + r) * SEQN + t]
                                 : x64[(size_t)(b0 + r) * SEQN + t];
            s.xi[r][t] = (int)idx;
        }
    }
    for (int j = tid; j < HIDN; j += TPB) {
        float a = hidden[(size_t)b0 * HIDN + j];
        float b = hidden[(size_t)(b0 + 1) * HIDN + j];
        s.hdup[j] = make_float4(a, a, b, b);
    }

    const int cpg = tid % NCPG;
    const int ch  = tid / NCPG;
    const int i0  = ch * NI;
    unsigned long long w0r[NI], w1r[NI];
    if (tid < NWRK) {
        const float* wp = Wh + (size_t)i0 * HIDN + 4 * cpg;
#pragma unroll
        for (int ii = 0; ii < NI; ii++) {
            w0r[ii] = *reinterpret_cast<const unsigned long long*>(wp + (size_t)ii * HIDN);
            w1r[ii] = *reinterpret_cast<const unsigned long long*>(wp + (size_t)ii * HIDN + 2);
        }
    }

    const int fc = tid % HIDN;
    const int fr = tid / HIDN;
    const size_t slab = (size_t)b0 << 10;   // b0 * 1024

    __syncthreads();

    // ================= scan loop (frozen) =================
    for (int t = 0; t < SEQN; t++) {
        if (tid < NWRK) {
            F2U a00, a01, a10, a11;
            a00.u = a01.u = a10.u = a11.u = 0ull;
            const ulonglong2* hp =
                reinterpret_cast<const ulonglong2*>(&s.hdup[i0]);
#pragma unroll
            for (int ii = 0; ii < NI; ii++) {
                ulonglong2 hd = hp[ii];
                fma2(a00.u, w0r[ii], hd.x);
                fma2(a01.u, w1r[ii], hd.x);
                fma2(a10.u, w0r[ii], hd.y);
                fma2(a11.u, w1r[ii], hd.y);
            }
            s.part[ch][0][cpg] = make_float4(a00.f2.x, a00.f2.y, a01.f2.x, a01.f2.y);
            s.part[ch][1][cpg] = make_float4(a10.f2.x, a10.f2.y, a11.f2.x, a11.f2.y);
        }
        __syncthreads();

        if (tid < 2 * HIDN) {
            const float* pb = reinterpret_cast<const float*>(s.part);
            float sum = 0.f;
#pragma unroll
            for (int c = 0; c < NCHK; c++)
                sum += pb[((c * 2 + fr) * NCPG + (fc >> 2)) * 4 + (fc & 3)];
            const int xi = s.xi[fr][t];
            float h = fast_tanh(sum + s.e2[xi * HIDN + fc]);
            F2U hh; hh.f2 = make_float2(h, h);
            *reinterpret_cast<unsigned long long*>(
                reinterpret_cast<char*>(&s.hdup[fc]) + fr * 8) = hh.u;
            // block-interleaved write: plane fc>>3, row slab + fr*1024 + t
            d_H2[((size_t)(fc >> 3) * NROWS + slab + ((size_t)fr << 10) + t) * 8
                 + (fc & 7)] = h;
            if (write_h && t == SEQN - 1)
                out_hidden[(size_t)(b0 + fr) * HIDN + fc] = h;
        }
        __syncthreads();
    }

    // ================= fused logits tail v6 =================
    // Rows r = fr*1024 + t (0..2047), CTA-private. Coalesced 32B/thread reads
    // from each ob-plane.
    float* Obase = out_logits + (size_t)b0 * SEQN * VOCABN;

#pragma unroll 1
    for (int pass = 1; pass >= 0; pass--) {
        const int rA = pass * 1024 + tid;
        const int rB = rA + 512;

        F2U accA[17], accB[17];
#pragma unroll
        for (int p = 0; p < 17; p++) { accA[p].u = 0ull; accB[p].u = 0ull; }

#pragma unroll 1
        for (int ob = 0; ob < NOB; ob++) {
            const float4* pl = reinterpret_cast<const float4*>(
                &d_H2[((size_t)ob * NROWS + slab) * 8]);
            float4 a0 = pl[2 * rA], a1 = pl[2 * rA + 1];
            float4 c0 = pl[2 * rB], c1 = pl[2 * rB + 1];
            const float eA[8] = {a0.x, a0.y, a0.z, a0.w, a1.x, a1.y, a1.z, a1.w};
            const float eB[8] = {c0.x, c0.y, c0.z, c0.w, c1.x, c1.y, c1.z, c1.w};
#pragma unroll
            for (int e = 0; e < 8; e++) {
                const int i = ob * 8 + e;
                const unsigned long long hdA = pack2(eA[e]);
                const unsigned long long hdB = pack2(eB[e]);
                const ulonglong2* wp2 =
                    reinterpret_cast<const ulonglong2*>(&s.wop[i * WOPW]);
#pragma unroll
                for (int q = 0; q < 8; q++) {
                    ulonglong2 w = wp2[q];
                    fma2(accA[2 * q].u,     w.x, hdA);
                    fma2(accA[2 * q + 1].u, w.y, hdA);
                    fma2(accB[2 * q].u,     w.x, hdB);
                    fma2(accB[2 * q + 1].u, w.y, hdB);
                }
                unsigned long long wl =
                    *reinterpret_cast<const unsigned long long*>(&s.wop[i * WOPW + 32]);
                fma2(accA[16].u, wl, hdA);
                fma2(accB[16].u, wl, hdB);
            }
        }

        // scalar stores: logit rows are 132 bytes, odd rows not 8B-aligned
        float* oA = Obase + (size_t)rA * VOCABN;
        float* oB = Obase + (size_t)rB * VOCABN;
#pragma unroll
        for (int p = 0; p < 16; p++) {
            oA[2 * p]     = accA[p].f2.x;
            oA[2 * p + 1] = accA[p].f2.y;
            oB[2 * p]     = accB[p].f2.x;
            oB[2 * p + 1] = accB[p].f2.y;
        }
        oA[32] = accA[16].f2.x;
        oB[32] = accB[16].f2.x;
    }
}

// ---------------------------------------------------------------------------
extern "C" void kernel_launch(void* const* d_in, const int* in_sizes, int n_in,
                              void* d_out, int out_size) {
    const void*  x      = d_in[0];
    const float* hidden = (const float*)d_in[1];
    const float* emb    = (const float*)d_in[2];
    const float* We     = (const float*)d_in[3];
    const float* Wh     = (const float*)d_in[4];
    const float* Wo     = (const float*)d_in[5];

    float* logits = (float*)d_out;
    const long long LOGITS_ELEMS = (long long)BATCHN * SEQN * VOCABN;
    int write_h = (out_size >= (int)(LOGITS_ELEMS + BATCHN * HIDN));
    float* outh = logits + LOGITS_ELEMS;

    const int prep_smem = (HIDN * HIDN + HIDN) * (int)sizeof(float);
    cudaFuncSetAttribute((const void*)prep_kernel,
                         cudaFuncAttributeMaxDynamicSharedMemorySize, prep_smem);
    prep_kernel<<<VOCABN + 1, 256, prep_smem>>>(emb, We, Wo, (const int*)x);

    cudaFuncSetAttribute((const void*)scan_kernel,
                         cudaFuncAttributeMaxDynamicSharedMemorySize,
                         (int)sizeof(Smem));
    scan_kernel<<<BATCHN / 2, TPB, sizeof(Smem)>>>(
        x, hidden, Wh, logits, outh, write_h);
}

// round 17
// speedup vs baseline: 2.1730x; 1.0285x over previous
#include <cuda_runtime.h>

#define BATCHN 256
#define SEQN   1024
#define HIDN   200
#define VOCABN 33

#define NCPG  50            // col groups of 4: 50*4 = 200
#define NCHK  10            // i-chunks of 20
#define NI    20
#define NWRK  500
#define TPB   512

#define WOPW  36            // padded W_o row (33 -> 36)
#define NROWS ((size_t)BATCHN * SEQN)   // 262144 global h-rows
#define NOB   (HIDN / 8)    // 25 ob-planes

__device__ float d_E2[VOCABN * HIDN];
__device__ float d_wop[HIDN * WOPW];
__device__ int   d_x_is32 = 0;
// Block-interleaved H: d_H2[(ob*NROWS + globalrow)*8 + lane], 210MB
__device__ float d_H2[(size_t)NOB * NROWS * 8];

union F2U { unsigned long long u; float2 f2; };

__device__ __forceinline__ void fma2(unsigned long long& d,
                                     unsigned long long a,
                                     unsigned long long b) {
    asm("fma.rn.f32x2 %0, %1, %2, %0;" : "+l"(d) : "l"(a), "l"(b));
}
__device__ __forceinline__ unsigned long long pack2(float x) {
    F2U r; r.f2 = make_float2(x, x); return r.u;
}
// single-MUFU tanh: shortens the phase-2 dependency chain vs EX2+RCP form
__device__ __forceinline__ float fast_tanh(float x) {
    float y;
    asm("tanh.approx.f32 %0, %1;" : "=f"(y) : "f"(x));
    return y;
}

// ---------------------------------------------------------------------------
// prep (merged): blocks 0..32 -> E2 rows (We staged in smem, coalesced);
// block 33 -> wop fill; block 0 also does is32 detection.
// ---------------------------------------------------------------------------
__global__ void prep_kernel(const float* __restrict__ emb,
                            const float* __restrict__ We,
                            const float* __restrict__ Wo,
                            const int* __restrict__ x32) {
    extern __shared__ float psh[];          // [200*200] We + [200] emb row
    const int v = blockIdx.x, tid = threadIdx.x;

    if (v == 33) {
        for (int k = tid; k < HIDN * WOPW; k += 256) {
            int i = k / WOPW, vv = k % WOPW;
            d_wop[k] = (vv < VOCABN) ? Wo[i * VOCABN + vv] : 0.f;
        }
        return;
    }

    float* wsh = psh;
    float* esh = psh + HIDN * HIDN;

    if (v == 0 && tid < 128) {
        unsigned any = __ballot_sync(0xffffffffu, x32[2 * tid + 1] != 0);
        if ((tid & 31) == 0 && any) atomicOr(&d_x_is32, 1);
    }
    const float4* w4 = reinterpret_cast<const float4*>(We);
    float4* s4 = reinterpret_cast<float4*>(wsh);
    for (int k = tid; k < HIDN * HIDN / 4; k += 256) s4[k] = w4[k];
    for (int k = tid; k < HIDN; k += 256) esh[k] = emb[v * HIDN + k];
    __syncthreads();

    for (int j = tid; j < HIDN; j += 256) {
        float acc = 0.f;
#pragma unroll 8
        for (int e = 0; e < HIDN; e++)
            acc += esh[e] * wsh[e * HIDN + j];
        d_E2[v * HIDN + j] = acc;
    }
}

// ---------------------------------------------------------------------------
// Scan (frozen R13 champion loop; only tanh impl changed) + tail v6.
// ---------------------------------------------------------------------------
struct __align__(16) Smem {
    float4 hdup[HIDN];               // {h0,h0,h1,h1} per column
    float4 part[NCHK][2][NCPG];      // GEMV partials
    float  e2[VOCABN * HIDN];
    float  wop[HIDN * WOPW];         // padded W_o for the tail
    int    xi[2][SEQN];
};

extern __shared__ unsigned char smem_raw[];

__global__ void __launch_bounds__(TPB, 1)
scan_kernel(const void* __restrict__ xv,
            const float* __restrict__ hidden,
            const float* __restrict__ Wh,
            float* __restrict__ out_logits,
            float* __restrict__ out_hidden,
            int write_h) {
    Smem& s = *reinterpret_cast<Smem*>(smem_raw);
    const int tid = threadIdx.x;
    const int b0  = blockIdx.x * 2;

    // ---- setup ----
    for (int k = tid; k < VOCABN * HIDN; k += TPB) s.e2[k] = d_E2[k];
    for (int k = tid; k < HIDN * WOPW; k += TPB) s.wop[k] = d_wop[k];
    {
        const int is32 = d_x_is32;
        const int* __restrict__ x32 = (const int*)xv;
        const long long* __restrict__ x64 = (const long long*)xv;
        for (int k = tid; k < 2 * SEQN; k += TPB) {
            int r = k >> 10, t = k & (SEQN - 1);
            long long idx = is32 ? (long long)x32[(size_t)(b0 + r) * SEQN + t]
                                 : x64[(size_t)(b0 + r) * SEQN + t];
            s.xi[r][t] = (int)idx;
        }
    }
    for (int j = tid; j < HIDN; j += TPB) {
        float a = hidden[(size_t)b0 * HIDN + j];
        float b = hidden[(size_t)(b0 + 1) * HIDN + j];
        s.hdup[j] = make_float4(a, a, b, b);
    }

    const int cpg = tid % NCPG;
    const int ch  = tid / NCPG;
    const int i0  = ch * NI;
    unsigned long long w0r[NI], w1r[NI];
    if (tid < NWRK) {
        const float* wp = Wh + (size_t)i0 * HIDN + 4 * cpg;
#pragma unroll
        for (int ii = 0; ii < NI; ii++) {
            w0r[ii] = *reinterpret_cast<const unsigned long long*>(wp + (size_t)ii * HIDN);
            w1r[ii] = *reinterpret_cast<const unsigned long long*>(wp + (size_t)ii * HIDN + 2);
        }
    }

    const int fc = tid % HIDN;
    const int fr = tid / HIDN;
    const size_t slab = (size_t)b0 << 10;   // b0 * 1024

    __syncthreads();

    // ================= scan loop (frozen) =================
    for (int t = 0; t < SEQN; t++) {
        if (tid < NWRK) {
            F2U a00, a01, a10, a11;
            a00.u = a01.u = a10.u = a11.u = 0ull;
            const ulonglong2* hp =
                reinterpret_cast<const ulonglong2*>(&s.hdup[i0]);
#pragma unroll
            for (int ii = 0; ii < NI; ii++) {
                ulonglong2 hd = hp[ii];
                fma2(a00.u, w0r[ii], hd.x);
                fma2(a01.u, w1r[ii], hd.x);
                fma2(a10.u, w0r[ii], hd.y);
                fma2(a11.u, w1r[ii], hd.y);
            }
            s.part[ch][0][cpg] = make_float4(a00.f2.x, a00.f2.y, a01.f2.x, a01.f2.y);
            s.part[ch][1][cpg] = make_float4(a10.f2.x, a10.f2.y, a11.f2.x, a11.f2.y);
        }
        __syncthreads();

        if (tid < 2 * HIDN) {
            const float* pb = reinterpret_cast<const float*>(s.part);
            float sum = 0.f;
#pragma unroll
            for (int c = 0; c < NCHK; c++)
                sum += pb[((c * 2 + fr) * NCPG + (fc >> 2)) * 4 + (fc & 3)];
            const int xi = s.xi[fr][t];
            float h = fast_tanh(sum + s.e2[xi * HIDN + fc]);
            F2U hh; hh.f2 = make_float2(h, h);
            *reinterpret_cast<unsigned long long*>(
                reinterpret_cast<char*>(&s.hdup[fc]) + fr * 8) = hh.u;
            d_H2[((size_t)(fc >> 3) * NROWS + slab + ((size_t)fr << 10) + t) * 8
                 + (fc & 7)] = h;
            if (write_h && t == SEQN - 1)
                out_hidden[(size_t)(b0 + fr) * HIDN + fc] = h;
        }
        __syncthreads();
    }

    // ================= fused logits tail v6 (frozen) =================
    float* Obase = out_logits + (size_t)b0 * SEQN * VOCABN;

#pragma unroll 1
    for (int pass = 1; pass >= 0; pass--) {
        const int rA = pass * 1024 + tid;
        const int rB = rA + 512;

        F2U accA[17], accB[17];
#pragma unroll
        for (int p = 0; p < 17; p++) { accA[p].u = 0ull; accB[p].u = 0ull; }

#pragma unroll 1
        for (int ob = 0; ob < NOB; ob++) {
            const float4* pl = reinterpret_cast<const float4*>(
                &d_H2[((size_t)ob * NROWS + slab) * 8]);
            float4 a0 = pl[2 * rA], a1 = pl[2 * rA + 1];
            float4 c0 = pl[2 * rB], c1 = pl[2 * rB + 1];
            const float eA[8] = {a0.x, a0.y, a0.z, a0.w, a1.x, a1.y, a1.z, a1.w};
            const float eB[8] = {c0.x, c0.y, c0.z, c0.w, c1.x, c1.y, c1.z, c1.w};
#pragma unroll
            for (int e = 0; e < 8; e++) {
                const int i = ob * 8 + e;
                const unsigned long long hdA = pack2(eA[e]);
                const unsigned long long hdB = pack2(eB[e]);
                const ulonglong2* wp2 =
                    reinterpret_cast<const ulonglong2*>(&s.wop[i * WOPW]);
#pragma unroll
                for (int q = 0; q < 8; q++) {
                    ulonglong2 w = wp2[q];
                    fma2(accA[2 * q].u,     w.x, hdA);
                    fma2(accA[2 * q + 1].u, w.y, hdA);
                    fma2(accB[2 * q].u,     w.x, hdB);
                    fma2(accB[2 * q + 1].u, w.y, hdB);
                }
                unsigned long long wl =
                    *reinterpret_cast<const unsigned long long*>(&s.wop[i * WOPW + 32]);
                fma2(accA[16].u, wl, hdA);
                fma2(accB[16].u, wl, hdB);
            }
        }

        // scalar stores: logit rows are 132 bytes, odd rows not 8B-aligned
        float* oA = Obase + (size_t)rA * VOCABN;
        float* oB = Obase + (size_t)rB * VOCABN;
#pragma unroll
        for (int p = 0; p < 16; p++) {
            oA[2 * p]     = accA[p].f2.x;
            oA[2 * p + 1] = accA[p].f2.y;
            oB[2 * p]     = accB[p].f2.x;
            oB[2 * p + 1] = accB[p].f2.y;
        }
        oA[32] = accA[16].f2.x;
        oB[32] = accB[16].f2.x;
    }
}

// ---------------------------------------------------------------------------
extern "C" void kernel_launch(void* const* d_in, const int* in_sizes, int n_in,
                              void* d_out, int out_size) {
    const void*  x      = d_in[0];
    const float* hidden = (const float*)d_in[1];
    const float* emb    = (const float*)d_in[2];
    const float* We     = (const float*)d_in[3];
    const float* Wh     = (const float*)d_in[4];
    const float* Wo     = (const float*)d_in[5];

    float* logits = (float*)d_out;
    const long long LOGITS_ELEMS = (long long)BATCHN * SEQN * VOCABN;
    int write_h = (out_size >= (int)(LOGITS_ELEMS + BATCHN * HIDN));
    float* outh = logits + LOGITS_ELEMS;

    const int prep_smem = (HIDN * HIDN + HIDN) * (int)sizeof(float);
    cudaFuncSetAttribute((const void*)prep_kernel,
                         cudaFuncAttributeMaxDynamicSharedMemorySize, prep_smem);
    prep_kernel<<<VOCABN + 1, 256, prep_smem>>>(emb, We, Wo, (const int*)x);

    cudaFuncSetAttribute((const void*)scan_kernel,
                         cudaFuncAttributeMaxDynamicSharedMemorySize,
                         (int)sizeof(Smem));
    scan_kernel<<<BATCHN / 2, TPB, sizeof(Smem)>>>(
        x, hidden, Wh, logits, outh, write_h);
}